// round 1
// baseline (speedup 1.0000x reference)
#include <cuda_runtime.h>
#include <math.h>

#define NP 16384
#define NR 8192

typedef unsigned long long ull;

// ---------------- scratch (static __device__, no allocation) ----------------
__device__ float g_bufA[384 * NP];
__device__ float g_bufB[384 * NP];
__device__ float g_buf2[256 * NP];
__device__ float g_full[160 * NP];
__device__ float g_fp[128 * NP];
__device__ float g_rgbT[NR * 128];
__device__ int   g_idx[NP * 3];

// ---------------- f32x2 helpers ----------------
__device__ __forceinline__ ull pack2(float x) {
    ull r; unsigned u = __float_as_uint(x);
    asm("mov.b64 %0, {%1, %1};" : "=l"(r) : "r"(u));
    return r;
}
__device__ __forceinline__ void fma2(ull& d, ull a, ull b) {
    asm("fma.rn.f32x2 %0, %1, %2, %0;" : "+l"(d) : "l"(a), "l"(b));
}
__device__ __forceinline__ float2 unpack2(ull v) {
    float lo, hi;
    asm("mov.b64 {%0, %1}, %2;" : "=f"(lo), "=f"(hi) : "l"(v));
    return make_float2(lo, hi);
}

// ---------------- 3-NN (16384 pcd x 8192 rgb) ----------------
__global__ __launch_bounds__(256) void knn_kernel(const float* __restrict__ pcd,
                                                  const float* __restrict__ rgb,
                                                  int* __restrict__ outIdx)
{
    __shared__ float4 srgb[1024];
    int n = blockIdx.x * blockDim.x + threadIdx.x;
    float px = pcd[n * 3 + 0], py = pcd[n * 3 + 1], pz = pcd[n * 3 + 2];
    float b0 = 1e30f, b1 = 1e30f, b2 = 1e30f;
    int   i0 = 0, i1 = 0, i2 = 0;

    for (int t = 0; t < NR; t += 1024) {
        __syncthreads();
        for (int q = threadIdx.x; q < 1024; q += blockDim.x) {
            int j = t + q;
            srgb[q] = make_float4(rgb[j * 3 + 0], rgb[j * 3 + 1], rgb[j * 3 + 2], 0.f);
        }
        __syncthreads();
        #pragma unroll 8
        for (int q = 0; q < 1024; q++) {
            float4 r = srgb[q];
            float dx = px - r.x, dy = py - r.y, dz = pz - r.z;
            float d2 = dx * dx;
            d2 = fmaf(dy, dy, d2);
            d2 = fmaf(dz, dz, d2);
            if (d2 < b2) {
                int idx = t + q;
                if (d2 < b0)      { b2 = b1; i2 = i1; b1 = b0; i1 = i0; b0 = d2; i0 = idx; }
                else if (d2 < b1) { b2 = b1; i2 = i1; b1 = d2; i1 = idx; }
                else              { b2 = d2; i2 = idx; }
            }
        }
    }
    // dist > radius -> shadow (-1)
    outIdx[n * 3 + 0] = (sqrtf(b0) > 0.075f) ? -1 : i0;
    outIdx[n * 3 + 1] = (sqrtf(b1) > 0.075f) ? -1 : i1;
    outIdx[n * 3 + 2] = (sqrtf(b2) > 0.075f) ? -1 : i2;
}

// ---------------- transpose rgb_features (128, NR) -> (NR, 128) ----------------
__global__ void transpose_kernel(const float* __restrict__ in, float* __restrict__ out)
{
    __shared__ float tile[32][33];
    int c0 = blockIdx.y * 32;
    int n0 = blockIdx.x * 32;
    #pragma unroll
    for (int i = 0; i < 32; i += 8)
        tile[threadIdx.y + i][threadIdx.x] = in[(c0 + threadIdx.y + i) * NR + n0 + threadIdx.x];
    __syncthreads();
    #pragma unroll
    for (int i = 0; i < 32; i += 8)
        out[(n0 + threadIdx.y + i) * 128 + c0 + threadIdx.x] = tile[threadIdx.x][threadIdx.y + i];
}

// ---------------- gather neighbor features -> x_cat (384,NP) + max (128,NP) ----------------
__global__ __launch_bounds__(256) void gather_kernel(const float* __restrict__ rgbT,
                                                     const int* __restrict__ idx,
                                                     float* __restrict__ xcat,
                                                     float* __restrict__ maxout)
{
    __shared__ float s[3 * 16 * 129];   // s[(j*16+p)*129 + c]
    int n0 = blockIdx.x * 16;
    for (int e = threadIdx.x; e < 3 * 16 * 128; e += blockDim.x) {
        int c  = e & 127;
        int pj = e >> 7;              // 0..47
        int p  = pj / 3, j = pj % 3;
        int row = idx[(n0 + p) * 3 + j];
        float v = (row >= 0) ? rgbT[row * 128 + c] : 0.f;
        s[(j * 16 + p) * 129 + c] = v;
    }
    __syncthreads();
    for (int w = threadIdx.x; w < 512 * 16; w += blockDim.x) {
        int p = w & 15;
        int row = w >> 4;
        if (row < 384) {
            int j = row >> 7, c = row & 127;
            xcat[row * NP + n0 + p] = s[(j * 16 + p) * 129 + c];
        } else {
            int c = row - 384;
            float v0 = s[(0 * 16 + p) * 129 + c];
            float v1 = s[(1 * 16 + p) * 129 + c];
            float v2 = s[(2 * 16 + p) * 129 + c];
            maxout[c * NP + n0 + p] = fmaxf(v0, fmaxf(v1, v2));
        }
    }
}

// ---------------- fused 1x1-conv GEMM: Y(M,NP) = W(M,K) @ X(K,NP), epilogue ----------------
// mode 0: +bias          mode 1: +bias, BN(eval), ReLU
__global__ __launch_bounds__(256) void gemm_kernel(int M, int K,
                                                   const float* __restrict__ W,
                                                   const float* __restrict__ X,
                                                   float* __restrict__ Y,
                                                   const float* __restrict__ bias,
                                                   const float* __restrict__ bn,
                                                   int mode)
{
    __shared__ float As[16][64];
    __shared__ float Bs[16][64];
    int tid = threadIdx.x;
    int tx = tid & 15, ty = tid >> 4;
    int n0 = blockIdx.x * 64;
    int m0 = blockIdx.y * 64;

    ull acc[4][2];
    #pragma unroll
    for (int i = 0; i < 4; i++) { acc[i][0] = 0ull; acc[i][1] = 0ull; }

    int lm  = tid >> 2;          // 0..63 (W row in tile)
    int lkq = (tid & 3) * 4;     // k quad within slab
    int lk  = tid >> 4;          // 0..15 (X row in slab)
    int lnq = (tid & 15) * 4;    // n quad

    bool wValid = (m0 + lm) < M;
    const float* wRow = W + (m0 + lm) * K + lkq;

    for (int k0 = 0; k0 < K; k0 += 16) {
        float4 w4 = wValid ? *(const float4*)(wRow + k0) : make_float4(0.f, 0.f, 0.f, 0.f);
        float4 x4 = *(const float4*)(X + (k0 + lk) * NP + n0 + lnq);
        As[lkq + 0][lm] = w4.x;
        As[lkq + 1][lm] = w4.y;
        As[lkq + 2][lm] = w4.z;
        As[lkq + 3][lm] = w4.w;
        *(float4*)&Bs[lk][lnq] = x4;
        __syncthreads();
        #pragma unroll
        for (int kk = 0; kk < 16; kk++) {
            float4 av = *(const float4*)&As[kk][ty * 4];
            ulonglong2 bv = *(const ulonglong2*)&Bs[kk][tx * 4];
            ull a0 = pack2(av.x), a1 = pack2(av.y), a2 = pack2(av.z), a3 = pack2(av.w);
            fma2(acc[0][0], a0, bv.x); fma2(acc[0][1], a0, bv.y);
            fma2(acc[1][0], a1, bv.x); fma2(acc[1][1], a1, bv.y);
            fma2(acc[2][0], a2, bv.x); fma2(acc[2][1], a2, bv.y);
            fma2(acc[3][0], a3, bv.x); fma2(acc[3][1], a3, bv.y);
        }
        __syncthreads();
    }

    #pragma unroll
    for (int i = 0; i < 4; i++) {
        int m = m0 + ty * 4 + i;
        if (m < M) {
            float b = bias[m];
            float sc = 1.f, sh = b;
            if (mode == 1) {
                float g  = bn[0 * M + m];
                float be = bn[1 * M + m];
                float mn = bn[2 * M + m];
                float v  = bn[3 * M + m];
                float inv = g * rsqrtf(v + 1e-5f);
                sc = inv;
                sh = (b - mn) * inv + be;
            }
            #pragma unroll
            for (int j2 = 0; j2 < 2; j2++) {
                float2 p = unpack2(acc[i][j2]);
                float y0 = p.x * sc + sh;
                float y1 = p.y * sc + sh;
                if (mode == 1) { y0 = fmaxf(y0, 0.f); y1 = fmaxf(y1, 0.f); }
                int n = n0 + tx * 4 + j2 * 2;
                *(float2*)(Y + m * NP + n) = make_float2(y0, y1);
            }
        }
    }
}

// ---------------- score head: sigmoid(sh2_w . s + b) ----------------
__global__ __launch_bounds__(256) void score_kernel(const float* __restrict__ s,
                                                    const float* __restrict__ w,
                                                    const float* __restrict__ b,
                                                    float* __restrict__ out)
{
    int n = blockIdx.x * blockDim.x + threadIdx.x;
    float sum = 0.f;
    #pragma unroll 16
    for (int c = 0; c < 128; c++) sum = fmaf(w[c], s[c * NP + n], sum);
    float z = sum + b[0];
    out[n] = 1.f / (1.f + expf(-z));
}

// ---------------- L2 normalize fp^T -> vf (NP, 128) ----------------
__global__ __launch_bounds__(256) void normalize_kernel(const float* __restrict__ fp,
                                                        float* __restrict__ out)
{
    __shared__ float sft[128 * 33];
    __shared__ float sinv[32];
    int n0 = blockIdx.x * 32;
    for (int e = threadIdx.x; e < 128 * 32; e += blockDim.x) {
        int c = e >> 5, p = e & 31;
        sft[c * 33 + p] = fp[c * NP + n0 + p];
    }
    __syncthreads();
    if (threadIdx.x < 32) {
        int p = threadIdx.x;
        float sum = 0.f;
        #pragma unroll 16
        for (int c = 0; c < 128; c++) { float v = sft[c * 33 + p]; sum = fmaf(v, v, sum); }
        sinv[p] = 1.f / fmaxf(sqrtf(sum), 1e-12f);
    }
    __syncthreads();
    for (int e = threadIdx.x; e < 128 * 32; e += blockDim.x) {
        int p = e >> 7, c = e & 127;
        out[(n0 + p) * 128 + c] = sft[c * 33 + p] * sinv[p];
    }
}

// ---------------- launch ----------------
extern "C" void kernel_launch(void* const* d_in, const int* in_sizes, int n_in,
                              void* d_out, int out_size)
{
    const float* pcd_xyz  = (const float*)d_in[0];
    const float* rgb_xyz  = (const float*)d_in[1];
    const float* pcd_feat = (const float*)d_in[2];
    const float* rgb_feat = (const float*)d_in[3];
    const float* cc1_w = (const float*)d_in[4];
    const float* cc1_b = (const float*)d_in[5];
    const float* cc_bn = (const float*)d_in[6];
    const float* cc2_w = (const float*)d_in[7];
    const float* cc2_b = (const float*)d_in[8];
    const float* co1_w = (const float*)d_in[9];
    const float* co1_b = (const float*)d_in[10];
    const float* co_bn = (const float*)d_in[11];
    const float* co2_w = (const float*)d_in[12];
    const float* co2_b = (const float*)d_in[13];
    const float* dh1_w = (const float*)d_in[14];
    const float* dh1_b = (const float*)d_in[15];
    const float* dh1_bn = (const float*)d_in[16];
    const float* dh2_w = (const float*)d_in[17];
    const float* dh2_b = (const float*)d_in[18];
    const float* dh2_bn = (const float*)d_in[19];
    const float* dh3_w = (const float*)d_in[20];
    const float* dh3_b = (const float*)d_in[21];
    const float* sh1_w = (const float*)d_in[22];
    const float* sh1_b = (const float*)d_in[23];
    const float* sh_bn = (const float*)d_in[24];
    const float* sh2_w = (const float*)d_in[25];
    const float* sh2_b = (const float*)d_in[26];

    float *bufA, *bufB, *buf2, *fullb, *fpb, *rgbT;
    int* idx;
    cudaGetSymbolAddress((void**)&bufA,  g_bufA);
    cudaGetSymbolAddress((void**)&bufB,  g_bufB);
    cudaGetSymbolAddress((void**)&buf2,  g_buf2);
    cudaGetSymbolAddress((void**)&fullb, g_full);
    cudaGetSymbolAddress((void**)&fpb,   g_fp);
    cudaGetSymbolAddress((void**)&rgbT,  g_rgbT);
    cudaGetSymbolAddress((void**)&idx,   g_idx);

    float* out = (float*)d_out;

    // 3-NN + feature staging
    knn_kernel<<<NP / 256, 256>>>(pcd_xyz, rgb_xyz, idx);
    transpose_kernel<<<dim3(NR / 32, 128 / 32), dim3(32, 8)>>>(rgb_feat, rgbT);
    gather_kernel<<<NP / 16, 256>>>(rgbT, idx, bufA, buf2 + 128 * NP);

    // fuception + fusion + direct header + score header GEMM chain
    gemm_kernel<<<dim3(NP / 64, 6), 256>>>(384, 384, cc1_w, bufA, bufB, cc1_b, cc_bn, 1);
    gemm_kernel<<<dim3(NP / 64, 2), 256>>>(128, 384, cc2_w, bufB, buf2, cc2_b, nullptr, 0);
    gemm_kernel<<<dim3(NP / 64, 4), 256>>>(256, 256, co1_w, buf2, bufA, co1_b, co_bn, 1);
    cudaMemcpyAsync(fullb, pcd_feat, 32 * NP * sizeof(float), cudaMemcpyDeviceToDevice, 0);
    gemm_kernel<<<dim3(NP / 64, 2), 256>>>(128, 256, co2_w, bufA, fullb + 32 * NP, co2_b, nullptr, 0);
    gemm_kernel<<<dim3(NP / 64, 3), 256>>>(160, 160, dh1_w, fullb, bufA, dh1_b, dh1_bn, 1);
    gemm_kernel<<<dim3(NP / 64, 3), 256>>>(160, 160, dh2_w, bufA, bufB, dh2_b, dh2_bn, 1);
    gemm_kernel<<<dim3(NP / 64, 2), 256>>>(128, 160, dh3_w, bufB, fpb, dh3_b, nullptr, 0);
    gemm_kernel<<<dim3(NP / 64, 2), 256>>>(128, 128, sh1_w, fpb, bufA, sh1_b, sh_bn, 1);

    // outputs: [pcd_xyz (NP*3)] [vote_scores (NP)] [vf (NP*128)]
    score_kernel<<<NP / 256, 256>>>(bufA, sh2_w, sh2_b, out + NP * 3);
    normalize_kernel<<<NP / 32, 256>>>(fpb, out + NP * 3 + NP);
    cudaMemcpyAsync(out, pcd_xyz, NP * 3 * sizeof(float), cudaMemcpyDeviceToDevice, 0);
}

// round 2
// speedup vs baseline: 1.2545x; 1.2545x over previous
#include <cuda_runtime.h>
#include <math.h>

#define NP 16384
#define NR 8192

typedef unsigned long long ull;

// ---------------- scratch (static __device__, no allocation) ----------------
__device__ float g_bufA[384 * NP];
__device__ float g_bufB[384 * NP];
__device__ float g_buf2[256 * NP];
__device__ float g_full[160 * NP];
__device__ float g_fp[128 * NP];
__device__ float g_rgbT[NR * 128];
__device__ int   g_idx[NP * 3];

// ---------------- f32x2 helpers ----------------
__device__ __forceinline__ ull pack2(float x) {
    ull r; unsigned u = __float_as_uint(x);
    asm("mov.b64 %0, {%1, %1};" : "=l"(r) : "r"(u));
    return r;
}
__device__ __forceinline__ void fma2(ull& d, ull a, ull b) {
    asm("fma.rn.f32x2 %0, %1, %2, %0;" : "+l"(d) : "l"(a), "l"(b));
}
__device__ __forceinline__ float2 unpack2(ull v) {
    float lo, hi;
    asm("mov.b64 {%0, %1}, %2;" : "=f"(lo), "=f"(hi) : "l"(v));
    return make_float2(lo, hi);
}

// ---------------- 3-NN: 128 blocks x 256 threads; 2 threads/point ----------------
__global__ __launch_bounds__(256) void knn_kernel(const float* __restrict__ pcd,
                                                  const float* __restrict__ rgb,
                                                  int* __restrict__ outIdx)
{
    __shared__ float4 srgb[2048];          // [0..1023] lower half, [1024..2047] upper half
    __shared__ float  md[256 * 3];
    __shared__ int    mi[256 * 3];

    int tid  = threadIdx.x;
    int p    = blockIdx.x * 128 + (tid & 127);
    int half = tid >> 7;                   // 0: rgb [0,4096), 1: rgb [4096,8192)

    float px = pcd[p * 3 + 0], py = pcd[p * 3 + 1], pz = pcd[p * 3 + 2];
    float b0 = 1e30f, b1 = 1e30f, b2 = 1e30f;
    int   i0 = 0, i1 = 0, i2 = 0;

    for (int r = 0; r < 4; r++) {
        __syncthreads();
        // load both halves' tiles: 2048 float4, 8 per thread
        for (int q = tid; q < 2048; q += 256) {
            int j = (q >= 1024 ? 4096 - 1024 : 0) + r * 1024 + q;   // q<1024: r*1024+q ; else 4096+r*1024+(q-1024)
            srgb[q] = make_float4(rgb[j * 3 + 0], rgb[j * 3 + 1], rgb[j * 3 + 2], 0.f);
        }
        __syncthreads();
        const float4* tile = srgb + half * 1024;
        int base = half * 4096 + r * 1024;
        #pragma unroll 8
        for (int q = 0; q < 1024; q++) {
            float4 rr = tile[q];
            float dx = px - rr.x, dy = py - rr.y, dz = pz - rr.z;
            float d2 = dx * dx;
            d2 = fmaf(dy, dy, d2);
            d2 = fmaf(dz, dz, d2);
            if (d2 < b2) {
                int idx = base + q;
                if (d2 < b0)      { b2 = b1; i2 = i1; b1 = b0; i1 = i0; b0 = d2; i0 = idx; }
                else if (d2 < b1) { b2 = b1; i2 = i1; b1 = d2; i1 = idx; }
                else              { b2 = d2; i2 = idx; }
            }
        }
    }

    md[tid * 3 + 0] = b0; md[tid * 3 + 1] = b1; md[tid * 3 + 2] = b2;
    mi[tid * 3 + 0] = i0; mi[tid * 3 + 1] = i1; mi[tid * 3 + 2] = i2;
    __syncthreads();

    if (tid < 128) {
        // merge own (lower-half, lower indices) with partner's; tie -> lower index = A
        float a[3] = {b0, b1, b2};
        int   ai[3] = {i0, i1, i2};
        float bb[3] = {md[(tid + 128) * 3 + 0], md[(tid + 128) * 3 + 1], md[(tid + 128) * 3 + 2]};
        int   bi[3] = {mi[(tid + 128) * 3 + 0], mi[(tid + 128) * 3 + 1], mi[(tid + 128) * 3 + 2]};
        int ia = 0, ib = 0;
        #pragma unroll
        for (int t = 0; t < 3; t++) {
            bool takeA = (ib >= 3) || (ia < 3 && a[ia] <= bb[ib]);
            float rd = takeA ? a[ia] : bb[ib];
            int   ri = takeA ? ai[ia] : bi[ib];
            if (takeA) ia++; else ib++;
            outIdx[p * 3 + t] = (sqrtf(rd) > 0.075f) ? -1 : ri;
        }
    }
}

// ---------------- transpose rgb_features (128, NR) -> (NR, 128) ----------------
__global__ void transpose_kernel(const float* __restrict__ in, float* __restrict__ out)
{
    __shared__ float tile[32][33];
    int c0 = blockIdx.y * 32;
    int n0 = blockIdx.x * 32;
    #pragma unroll
    for (int i = 0; i < 32; i += 8)
        tile[threadIdx.y + i][threadIdx.x] = in[(c0 + threadIdx.y + i) * NR + n0 + threadIdx.x];
    __syncthreads();
    #pragma unroll
    for (int i = 0; i < 32; i += 8)
        out[(n0 + threadIdx.y + i) * 128 + c0 + threadIdx.x] = tile[threadIdx.x][threadIdx.y + i];
}

// ---------------- gather neighbor features -> x_cat (384,NP) + max (128,NP) ----------------
__global__ __launch_bounds__(256) void gather_kernel(const float* __restrict__ rgbT,
                                                     const int* __restrict__ idx,
                                                     float* __restrict__ xcat,
                                                     float* __restrict__ maxout)
{
    __shared__ float s[3 * 16 * 129];   // s[(j*16+p)*129 + c]
    int n0 = blockIdx.x * 16;
    for (int e = threadIdx.x; e < 3 * 16 * 128; e += blockDim.x) {
        int c  = e & 127;
        int pj = e >> 7;              // 0..47
        int p  = pj / 3, j = pj % 3;
        int row = idx[(n0 + p) * 3 + j];
        float v = (row >= 0) ? rgbT[row * 128 + c] : 0.f;
        s[(j * 16 + p) * 129 + c] = v;
    }
    __syncthreads();
    for (int w = threadIdx.x; w < 512 * 16; w += blockDim.x) {
        int p = w & 15;
        int row = w >> 4;
        if (row < 384) {
            int j = row >> 7, c = row & 127;
            xcat[row * NP + n0 + p] = s[(j * 16 + p) * 129 + c];
        } else {
            int c = row - 384;
            float v0 = s[(0 * 16 + p) * 129 + c];
            float v1 = s[(1 * 16 + p) * 129 + c];
            float v2 = s[(2 * 16 + p) * 129 + c];
            maxout[c * NP + n0 + p] = fmaxf(v0, fmaxf(v1, v2));
        }
    }
}

// ---------------- fused 1x1-conv GEMM v2: 128x128 tile, 8x8/thread, f32x2 ----------------
// Y(M,NP) = W(M,K) @ X(K,NP).  mode 0: +bias   mode 1: +bias, BN(eval), ReLU
__global__ __launch_bounds__(256) void gemm_kernel(int M, int K,
                                                   const float* __restrict__ W,
                                                   const float* __restrict__ X,
                                                   float* __restrict__ Y,
                                                   const float* __restrict__ bias,
                                                   const float* __restrict__ bn,
                                                   int mode)
{
    __shared__ float As[8][128];
    __shared__ float Bs[8][128];
    int tid = threadIdx.x;
    int tx = tid & 15, ty = tid >> 4;
    int n0 = blockIdx.x * 128;
    int m0 = blockIdx.y * 128;

    ull acc[8][4];
    #pragma unroll
    for (int i = 0; i < 8; i++)
        #pragma unroll
        for (int j = 0; j < 4; j++) acc[i][j] = 0ull;

    // gmem loaders
    int lkB = tid >> 5;                 // 0..7
    int lnB = (tid & 31) * 4;           // 0..124
    int lmA = tid >> 1;                 // 0..127
    int lkA = (tid & 1) * 4;            // 0 or 4
    const float* xPtr = X + lkB * NP + n0 + lnB;
    bool wV = (m0 + lmA) < M;
    const float* wPtr = W + (wV ? (m0 + lmA) : 0) * K + lkA;

    int nSlabs = K >> 3;
    float4 wReg = wV ? *(const float4*)wPtr : make_float4(0.f, 0.f, 0.f, 0.f);
    float4 xReg = *(const float4*)xPtr;

    for (int s = 0; s < nSlabs; s++) {
        As[lkA + 0][lmA] = wReg.x;
        As[lkA + 1][lmA] = wReg.y;
        As[lkA + 2][lmA] = wReg.z;
        As[lkA + 3][lmA] = wReg.w;
        *(float4*)&Bs[lkB][lnB] = xReg;
        __syncthreads();

        if (s + 1 < nSlabs) {
            wReg = wV ? *(const float4*)(wPtr + (s + 1) * 8) : make_float4(0.f, 0.f, 0.f, 0.f);
            xReg = *(const float4*)(xPtr + (size_t)(s + 1) * 8 * NP);
        }

        #pragma unroll
        for (int kk = 0; kk < 8; kk++) {
            float4 aA = *(const float4*)&As[kk][ty * 4];
            float4 aB = *(const float4*)&As[kk][64 + ty * 4];
            ulonglong2 bA = *(const ulonglong2*)&Bs[kk][tx * 4];
            ulonglong2 bB = *(const ulonglong2*)&Bs[kk][64 + tx * 4];
            ull a0 = pack2(aA.x), a1 = pack2(aA.y), a2 = pack2(aA.z), a3 = pack2(aA.w);
            ull a4 = pack2(aB.x), a5 = pack2(aB.y), a6 = pack2(aB.z), a7 = pack2(aB.w);
            fma2(acc[0][0], a0, bA.x); fma2(acc[0][1], a0, bA.y); fma2(acc[0][2], a0, bB.x); fma2(acc[0][3], a0, bB.y);
            fma2(acc[1][0], a1, bA.x); fma2(acc[1][1], a1, bA.y); fma2(acc[1][2], a1, bB.x); fma2(acc[1][3], a1, bB.y);
            fma2(acc[2][0], a2, bA.x); fma2(acc[2][1], a2, bA.y); fma2(acc[2][2], a2, bB.x); fma2(acc[2][3], a2, bB.y);
            fma2(acc[3][0], a3, bA.x); fma2(acc[3][1], a3, bA.y); fma2(acc[3][2], a3, bB.x); fma2(acc[3][3], a3, bB.y);
            fma2(acc[4][0], a4, bA.x); fma2(acc[4][1], a4, bA.y); fma2(acc[4][2], a4, bB.x); fma2(acc[4][3], a4, bB.y);
            fma2(acc[5][0], a5, bA.x); fma2(acc[5][1], a5, bA.y); fma2(acc[5][2], a5, bB.x); fma2(acc[5][3], a5, bB.y);
            fma2(acc[6][0], a6, bA.x); fma2(acc[6][1], a6, bA.y); fma2(acc[6][2], a6, bB.x); fma2(acc[6][3], a6, bB.y);
            fma2(acc[7][0], a7, bA.x); fma2(acc[7][1], a7, bA.y); fma2(acc[7][2], a7, bB.x); fma2(acc[7][3], a7, bB.y);
        }
        __syncthreads();
    }

    #pragma unroll
    for (int r = 0; r < 8; r++) {
        int m = m0 + ty * 4 + (r & 3) + ((r >> 2) << 6);
        if (m < M) {
            float b = bias[m];
            float sc = 1.f, sh = b;
            if (mode == 1) {
                float g  = bn[0 * M + m];
                float be = bn[1 * M + m];
                float mn = bn[2 * M + m];
                float v  = bn[3 * M + m];
                float inv = g * rsqrtf(v + 1e-5f);
                sc = inv;
                sh = (b - mn) * inv + be;
            }
            #pragma unroll
            for (int c = 0; c < 4; c++) {
                float2 p = unpack2(acc[r][c]);
                float y0 = p.x * sc + sh;
                float y1 = p.y * sc + sh;
                if (mode == 1) { y0 = fmaxf(y0, 0.f); y1 = fmaxf(y1, 0.f); }
                int n = n0 + tx * 4 + ((c & 1) << 1) + ((c >> 1) << 6);
                *(float2*)(Y + (size_t)m * NP + n) = make_float2(y0, y1);
            }
        }
    }
}

// ---------------- score head: sigmoid(sh2_w . s + b) ----------------
__global__ __launch_bounds__(256) void score_kernel(const float* __restrict__ s,
                                                    const float* __restrict__ w,
                                                    const float* __restrict__ b,
                                                    float* __restrict__ out)
{
    int n = blockIdx.x * blockDim.x + threadIdx.x;
    float sum = 0.f;
    #pragma unroll 16
    for (int c = 0; c < 128; c++) sum = fmaf(w[c], s[c * NP + n], sum);
    float z = sum + b[0];
    out[n] = 1.f / (1.f + expf(-z));
}

// ---------------- L2 normalize fp^T -> vf (NP, 128) ----------------
__global__ __launch_bounds__(256) void normalize_kernel(const float* __restrict__ fp,
                                                        float* __restrict__ out)
{
    __shared__ float sft[128 * 33];
    __shared__ float sinv[32];
    int n0 = blockIdx.x * 32;
    for (int e = threadIdx.x; e < 128 * 32; e += blockDim.x) {
        int c = e >> 5, p = e & 31;
        sft[c * 33 + p] = fp[c * NP + n0 + p];
    }
    __syncthreads();
    if (threadIdx.x < 32) {
        int p = threadIdx.x;
        float sum = 0.f;
        #pragma unroll 16
        for (int c = 0; c < 128; c++) { float v = sft[c * 33 + p]; sum = fmaf(v, v, sum); }
        sinv[p] = 1.f / fmaxf(sqrtf(sum), 1e-12f);
    }
    __syncthreads();
    for (int e = threadIdx.x; e < 128 * 32; e += blockDim.x) {
        int p = e >> 7, c = e & 127;
        out[(n0 + p) * 128 + c] = sft[c * 33 + p] * sinv[p];
    }
}

// ---------------- launch ----------------
extern "C" void kernel_launch(void* const* d_in, const int* in_sizes, int n_in,
                              void* d_out, int out_size)
{
    const float* pcd_xyz  = (const float*)d_in[0];
    const float* rgb_xyz  = (const float*)d_in[1];
    const float* pcd_feat = (const float*)d_in[2];
    const float* rgb_feat = (const float*)d_in[3];
    const float* cc1_w = (const float*)d_in[4];
    const float* cc1_b = (const float*)d_in[5];
    const float* cc_bn = (const float*)d_in[6];
    const float* cc2_w = (const float*)d_in[7];
    const float* cc2_b = (const float*)d_in[8];
    const float* co1_w = (const float*)d_in[9];
    const float* co1_b = (const float*)d_in[10];
    const float* co_bn = (const float*)d_in[11];
    const float* co2_w = (const float*)d_in[12];
    const float* co2_b = (const float*)d_in[13];
    const float* dh1_w = (const float*)d_in[14];
    const float* dh1_b = (const float*)d_in[15];
    const float* dh1_bn = (const float*)d_in[16];
    const float* dh2_w = (const float*)d_in[17];
    const float* dh2_b = (const float*)d_in[18];
    const float* dh2_bn = (const float*)d_in[19];
    const float* dh3_w = (const float*)d_in[20];
    const float* dh3_b = (const float*)d_in[21];
    const float* sh1_w = (const float*)d_in[22];
    const float* sh1_b = (const float*)d_in[23];
    const float* sh_bn = (const float*)d_in[24];
    const float* sh2_w = (const float*)d_in[25];
    const float* sh2_b = (const float*)d_in[26];

    float *bufA, *bufB, *buf2, *fullb, *fpb, *rgbT;
    int* idx;
    cudaGetSymbolAddress((void**)&bufA,  g_bufA);
    cudaGetSymbolAddress((void**)&bufB,  g_bufB);
    cudaGetSymbolAddress((void**)&buf2,  g_buf2);
    cudaGetSymbolAddress((void**)&fullb, g_full);
    cudaGetSymbolAddress((void**)&fpb,   g_fp);
    cudaGetSymbolAddress((void**)&rgbT,  g_rgbT);
    cudaGetSymbolAddress((void**)&idx,   g_idx);

    float* out = (float*)d_out;

    // 3-NN + feature staging
    knn_kernel<<<NP / 128, 256>>>(pcd_xyz, rgb_xyz, idx);
    transpose_kernel<<<dim3(NR / 32, 128 / 32), dim3(32, 8)>>>(rgb_feat, rgbT);
    gather_kernel<<<NP / 16, 256>>>(rgbT, idx, bufA, buf2 + 128 * NP);

    // fuception + fusion + direct header + score header GEMM chain
    gemm_kernel<<<dim3(NP / 128, 3), 256>>>(384, 384, cc1_w, bufA, bufB, cc1_b, cc_bn, 1);
    gemm_kernel<<<dim3(NP / 128, 1), 256>>>(128, 384, cc2_w, bufB, buf2, cc2_b, nullptr, 0);
    gemm_kernel<<<dim3(NP / 128, 2), 256>>>(256, 256, co1_w, buf2, bufA, co1_b, co_bn, 1);
    cudaMemcpyAsync(fullb, pcd_feat, 32 * NP * sizeof(float), cudaMemcpyDeviceToDevice, 0);
    gemm_kernel<<<dim3(NP / 128, 1), 256>>>(128, 256, co2_w, bufA, fullb + 32 * NP, co2_b, nullptr, 0);
    gemm_kernel<<<dim3(NP / 128, 2), 256>>>(160, 160, dh1_w, fullb, bufA, dh1_b, dh1_bn, 1);
    gemm_kernel<<<dim3(NP / 128, 2), 256>>>(160, 160, dh2_w, bufA, bufB, dh2_b, dh2_bn, 1);
    gemm_kernel<<<dim3(NP / 128, 1), 256>>>(128, 160, dh3_w, bufB, fpb, dh3_b, nullptr, 0);
    gemm_kernel<<<dim3(NP / 128, 1), 256>>>(128, 128, sh1_w, fpb, bufA, sh1_b, sh_bn, 1);

    // outputs: [pcd_xyz (NP*3)] [vote_scores (NP)] [vf (NP*128)]
    score_kernel<<<NP / 256, 256>>>(bufA, sh2_w, sh2_b, out + NP * 3);
    normalize_kernel<<<NP / 32, 256>>>(fpb, out + NP * 3 + NP);
    cudaMemcpyAsync(out, pcd_xyz, NP * 3 * sizeof(float), cudaMemcpyDeviceToDevice, 0);
}

// round 8
// speedup vs baseline: 1.9133x; 1.5252x over previous
#include <cuda_runtime.h>
#include <cuda_fp16.h>
#include <math.h>

#define NP 16384
#define NR 8192

typedef unsigned long long ull;

// ============================ scratch buffers ============================
__device__ __align__(16) float g_xcat[(size_t)NP * 384];
__device__ __align__(16) float g_h1  [(size_t)NP * 384];
__device__ __align__(16) float g_buf2[(size_t)NP * 256];   // cols 0-127 cc2 out, 128-255 max feats
__device__ __align__(16) float g_co1 [(size_t)NP * 256];
__device__ __align__(16) float g_full[(size_t)NP * 160];   // cols 0-31 pcd feats, 32-159 attach
__device__ __align__(16) float g_d1  [(size_t)NP * 160];
__device__ __align__(16) float g_d2  [(size_t)NP * 160];
__device__ __align__(16) float g_fp  [(size_t)NP * 128];
__device__ __align__(16) float g_s1  [(size_t)NP * 128];
__device__ __align__(16) float g_rgbT[(size_t)NR * 128];
__device__ int   g_idx [NP * 3];
// fp16 hi/lo weight planes (padded K)
#define WTOT 397312
__device__ __align__(16) __half g_whi[WTOT];
__device__ __align__(16) __half g_wlo[WTOT];

// ============================ helpers ============================
__device__ __forceinline__ unsigned pk(__half a, __half b) {
    __half2 t = __halves2half2(a, b);
    return *reinterpret_cast<unsigned*>(&t);
}
__device__ __forceinline__ void mma16816(float* d, const unsigned* a, const unsigned* b) {
    asm volatile("mma.sync.aligned.m16n8k16.row.col.f32.f16.f16.f32 "
        "{%0,%1,%2,%3}, {%4,%5,%6,%7}, {%8,%9}, {%0,%1,%2,%3};"
        : "+f"(d[0]), "+f"(d[1]), "+f"(d[2]), "+f"(d[3])
        : "r"(a[0]), "r"(a[1]), "r"(a[2]), "r"(a[3]), "r"(b[0]), "r"(b[1]));
}

// ============================ 3-NN ============================
__global__ __launch_bounds__(256) void knn_kernel(const float* __restrict__ pcd,
                                                  const float* __restrict__ rgb,
                                                  int* __restrict__ outIdx)
{
    __shared__ float4 srgb[2048];
    __shared__ float  md[256 * 3];
    __shared__ int    mi[256 * 3];
    int tid = threadIdx.x;
    int p = blockIdx.x * 128 + (tid & 127);
    int half = tid >> 7;
    float px = pcd[p * 3 + 0], py = pcd[p * 3 + 1], pz = pcd[p * 3 + 2];
    float b0 = 1e30f, b1 = 1e30f, b2 = 1e30f;
    int i0 = 0, i1 = 0, i2 = 0;
    for (int r = 0; r < 4; r++) {
        __syncthreads();
        for (int q = tid; q < 2048; q += 256) {
            int j = (q >= 1024 ? 3072 : 0) + r * 1024 + q;
            srgb[q] = make_float4(rgb[j * 3 + 0], rgb[j * 3 + 1], rgb[j * 3 + 2], 0.f);
        }
        __syncthreads();
        const float4* tile = srgb + half * 1024;
        int base = half * 4096 + r * 1024;
        #pragma unroll 8
        for (int q = 0; q < 1024; q++) {
            float4 rr = tile[q];
            float dx = px - rr.x, dy = py - rr.y, dz = pz - rr.z;
            float d2 = dx * dx; d2 = fmaf(dy, dy, d2); d2 = fmaf(dz, dz, d2);
            if (d2 < b2) {
                int idx = base + q;
                if (d2 < b0)      { b2 = b1; i2 = i1; b1 = b0; i1 = i0; b0 = d2; i0 = idx; }
                else if (d2 < b1) { b2 = b1; i2 = i1; b1 = d2; i1 = idx; }
                else              { b2 = d2; i2 = idx; }
            }
        }
    }
    md[tid * 3 + 0] = b0; md[tid * 3 + 1] = b1; md[tid * 3 + 2] = b2;
    mi[tid * 3 + 0] = i0; mi[tid * 3 + 1] = i1; mi[tid * 3 + 2] = i2;
    __syncthreads();
    if (tid < 128) {
        float a[3] = {b0, b1, b2}; int ai[3] = {i0, i1, i2};
        float bb[3] = {md[(tid + 128) * 3], md[(tid + 128) * 3 + 1], md[(tid + 128) * 3 + 2]};
        int bi[3] = {mi[(tid + 128) * 3], mi[(tid + 128) * 3 + 1], mi[(tid + 128) * 3 + 2]};
        int ia = 0, ib = 0;
        #pragma unroll
        for (int t = 0; t < 3; t++) {
            bool tA = (ib >= 3) || (ia < 3 && a[ia] <= bb[ib]);
            float rd = tA ? a[ia] : bb[ib];
            int ri = tA ? ai[ia] : bi[ib];
            if (tA) ia++; else ib++;
            outIdx[p * 3 + t] = (sqrtf(rd) > 0.075f) ? -1 : ri;
        }
    }
}

// ============================ staging kernels ============================
__global__ void transpose_rgb(const float* __restrict__ in, float* __restrict__ out)
{
    __shared__ float tile[32][33];
    int c0 = blockIdx.y * 32, n0 = blockIdx.x * 32;
    #pragma unroll
    for (int i = 0; i < 32; i += 8)
        tile[threadIdx.y + i][threadIdx.x] = in[(c0 + threadIdx.y + i) * NR + n0 + threadIdx.x];
    __syncthreads();
    #pragma unroll
    for (int i = 0; i < 32; i += 8)
        out[(n0 + threadIdx.y + i) * 128 + c0 + threadIdx.x] = tile[threadIdx.x][threadIdx.y + i];
}

__global__ void tpose_pcd(const float* __restrict__ in, float* __restrict__ out)
{
    __shared__ float t[32][33];
    int n0 = blockIdx.x * 32;
    int tx = threadIdx.x, ty = threadIdx.y;
    #pragma unroll
    for (int i = 0; i < 32; i += 8) t[ty + i][tx] = in[(ty + i) * NP + n0 + tx];
    __syncthreads();
    #pragma unroll
    for (int i = 0; i < 32; i += 8) out[(size_t)(n0 + ty + i) * 160 + tx] = t[tx][ty + i];
}

// xcat (NP, 384) row-major: row p = [nb0 feats | nb1 | nb2]
__global__ __launch_bounds__(256) void gather_kernel(const float* __restrict__ rgbT,
                                                     const int* __restrict__ idx,
                                                     float* __restrict__ xcat)
{
    int e = blockIdx.x * 256 + threadIdx.x;      // NP*3*32 threads
    int c4 = e & 31;
    int t = e >> 5;
    int p = t / 3, j = t - p * 3;
    int row = idx[p * 3 + j];
    float4 v = make_float4(0.f, 0.f, 0.f, 0.f);
    if (row >= 0) v = *(const float4*)(rgbT + (size_t)row * 128 + c4 * 4);
    *(float4*)(xcat + (size_t)p * 384 + j * 128 + c4 * 4) = v;
}

// max over 3 neighbors -> buf2 cols 128..255
// Reference semantics: shadowed neighbor contributes a ZERO row to the max;
// the max itself is over exactly those 3 values (can be negative).
__global__ __launch_bounds__(256) void maxfeat_kernel(const float* __restrict__ rgbT,
                                                      const int* __restrict__ idx,
                                                      float* __restrict__ buf2)
{
    int e = blockIdx.x * 256 + threadIdx.x;      // NP*32 threads
    int c4 = e & 31;
    int p = e >> 5;
    float4 m = make_float4(-1e30f, -1e30f, -1e30f, -1e30f);
    #pragma unroll
    for (int j = 0; j < 3; j++) {
        int row = idx[p * 3 + j];
        float4 v = make_float4(0.f, 0.f, 0.f, 0.f);
        if (row >= 0) v = *(const float4*)(rgbT + (size_t)row * 128 + c4 * 4);
        m.x = fmaxf(m.x, v.x); m.y = fmaxf(m.y, v.y);
        m.z = fmaxf(m.z, v.z); m.w = fmaxf(m.w, v.w);
    }
    *(float4*)(buf2 + (size_t)p * 256 + 128 + c4 * 4) = m;
}

// fused weight split fp32 -> fp16 hi/lo across all 8 layers
__global__ __launch_bounds__(256) void prep_all(
    const float* __restrict__ cc1, const float* __restrict__ cc2,
    const float* __restrict__ co1, const float* __restrict__ co2,
    const float* __restrict__ dh1, const float* __restrict__ dh2,
    const float* __restrict__ dh3, const float* __restrict__ sh1,
    __half* __restrict__ dhi, __half* __restrict__ dlo)
{
    int g = blockIdx.x * 256 + threadIdx.x;
    if (g >= WTOT) return;
    const float* src; int loc, K, Kpad;
    if      (g < 147456) { src = cc1; loc = g;          K = 384; Kpad = 384; }
    else if (g < 196608) { src = cc2; loc = g - 147456; K = 384; Kpad = 384; }
    else if (g < 262144) { src = co1; loc = g - 196608; K = 256; Kpad = 256; }
    else if (g < 294912) { src = co2; loc = g - 262144; K = 256; Kpad = 256; }
    else if (g < 325632) { src = dh1; loc = g - 294912; K = 160; Kpad = 192; }
    else if (g < 356352) { src = dh2; loc = g - 325632; K = 160; Kpad = 192; }
    else if (g < 380928) { src = dh3; loc = g - 356352; K = 160; Kpad = 192; }
    else                 { src = sh1; loc = g - 380928; K = 128; Kpad = 128; }
    int r = loc / Kpad, c = loc - r * Kpad;
    float x = (c < K) ? src[r * K + c] : 0.f;
    __half h = __float2half(x);
    __half l = __float2half(x - __half2float(h));
    dhi[g] = h; dlo[g] = l;
}

// ============================ HMMA GEMM (fp16 split, direct-LDS fragments) ============================
// Y[p, m] = sum_k X[p,k] * W[m,k]  (+bias, opt BN+ReLU)
// split precision: X = Xh + Xl (fp16), acc = XhWh + XlWh + XhWl (fp32)
// block: 128 pts x 128 cout; 8 warps, warp tile 32x64; K-slab 32
#define LDW 40   // fp16 stride per row (32 data + 8 pad) -> 80 B
__global__ __launch_bounds__(256, 2) void gemm_hmma(
    const float* __restrict__ X, int pitchA, int K, int Kpad,
    const __half* __restrict__ Whi, const __half* __restrict__ Wlo,
    int Cout, float* __restrict__ Y, int pitchY,
    const float* __restrict__ bias, const float* __restrict__ bn, int mode)
{
    __shared__ __align__(16) __half sAh[128 * LDW];
    __shared__ __align__(16) __half sAl[128 * LDW];
    __shared__ __align__(16) __half sBh[128 * LDW];
    __shared__ __align__(16) __half sBl[128 * LDW];
    __shared__ float sSc[128], sSh[128];

    const int tid = threadIdx.x;
    const int lane = tid & 31, wid = tid >> 5;
    const int wm = wid >> 1, wn = wid & 1;
    const int g = lane >> 2, tc = lane & 3;
    const int n0 = blockIdx.x * 128;
    const int nb0 = blockIdx.y * 128;
    const int NT = min(128, Cout - nb0);

    if (tid < 128) {
        float sc = 0.f, sh = 0.f;
        if (tid < NT) {
            int m = nb0 + tid;
            float b = bias[m];
            sc = 1.f; sh = b;
            if (mode) {
                float gg = bn[m], be = bn[Cout + m], mn = bn[2 * Cout + m], v = bn[3 * Cout + m];
                float inv = gg * rsqrtf(v + 1e-5f);
                sc = inv; sh = (b - mn) * inv + be;
            }
        }
        sSc[tid] = sc; sSh[tid] = sh;
    }

    float acc[2][8][4];
    #pragma unroll
    for (int a = 0; a < 2; a++)
        #pragma unroll
        for (int b = 0; b < 8; b++)
            #pragma unroll
            for (int c = 0; c < 4; c++) acc[a][b][c] = 0.f;

    const int slabs = Kpad >> 5;
    for (int sl = 0; sl < slabs; sl++) {
        int k0 = sl << 5;
        // --- A: 128 rows x 32 fp32 -> fp16 hi/lo ---
        #pragma unroll
        for (int i = 0; i < 4; i++) {
            int e = tid + i * 256;
            int row = e >> 3, c4 = (e & 7) * 4;
            int kc = k0 + c4;
            float4 v = make_float4(0.f, 0.f, 0.f, 0.f);
            if (kc < K) v = *(const float4*)(X + (size_t)(n0 + row) * pitchA + kc);
            __half h0 = __float2half(v.x), h1 = __float2half(v.y),
                   h2 = __float2half(v.z), h3 = __float2half(v.w);
            __half l0 = __float2half(v.x - __half2float(h0));
            __half l1 = __float2half(v.y - __half2float(h1));
            __half l2 = __float2half(v.z - __half2float(h2));
            __half l3 = __float2half(v.w - __half2float(h3));
            *(uint2*)&sAh[row * LDW + c4] = make_uint2(pk(h0, h1), pk(h2, h3));
            *(uint2*)&sAl[row * LDW + c4] = make_uint2(pk(l0, l1), pk(l2, l3));
        }
        // --- B: 128 rows x 32 fp16, hi+lo planes ---
        #pragma unroll
        for (int i = 0; i < 2; i++) {
            int e = tid + i * 256;
            int row = e >> 2, q8 = (e & 3) * 8;
            uint4 hh = make_uint4(0u, 0u, 0u, 0u), ll = make_uint4(0u, 0u, 0u, 0u);
            if (row < NT) {
                size_t go = (size_t)(nb0 + row) * Kpad + k0 + q8;
                hh = *(const uint4*)(Whi + go);
                ll = *(const uint4*)(Wlo + go);
            }
            *(uint4*)&sBh[row * LDW + q8] = hh;
            *(uint4*)&sBl[row * LDW + q8] = ll;
        }
        __syncthreads();

        #pragma unroll
        for (int s = 0; s < 2; s++) {
            const int kb = s * 16 + tc * 2;      // k element offset for this thread
            unsigned ah[2][4], al[2][4];
            #pragma unroll
            for (int mt = 0; mt < 2; mt++) {
                int r = wm * 32 + mt * 16 + g;
                ah[mt][0] = *(const unsigned*)&sAh[r * LDW + kb];
                ah[mt][1] = *(const unsigned*)&sAh[(r + 8) * LDW + kb];
                ah[mt][2] = *(const unsigned*)&sAh[r * LDW + kb + 8];
                ah[mt][3] = *(const unsigned*)&sAh[(r + 8) * LDW + kb + 8];
                al[mt][0] = *(const unsigned*)&sAl[r * LDW + kb];
                al[mt][1] = *(const unsigned*)&sAl[(r + 8) * LDW + kb];
                al[mt][2] = *(const unsigned*)&sAl[r * LDW + kb + 8];
                al[mt][3] = *(const unsigned*)&sAl[(r + 8) * LDW + kb + 8];
            }
            #pragma unroll
            for (int j8 = 0; j8 < 8; j8++) {
                int nrow = wn * 64 + j8 * 8 + g;
                unsigned bh[2], bl[2];
                bh[0] = *(const unsigned*)&sBh[nrow * LDW + kb];
                bh[1] = *(const unsigned*)&sBh[nrow * LDW + kb + 8];
                bl[0] = *(const unsigned*)&sBl[nrow * LDW + kb];
                bl[1] = *(const unsigned*)&sBl[nrow * LDW + kb + 8];
                #pragma unroll
                for (int mt = 0; mt < 2; mt++) {
                    mma16816(acc[mt][j8], ah[mt], bh);
                    mma16816(acc[mt][j8], al[mt], bh);
                    mma16816(acc[mt][j8], ah[mt], bl);
                }
            }
        }
        __syncthreads();
    }

    // --- epilogue ---
    #pragma unroll
    for (int mt = 0; mt < 2; mt++) {
        int r0 = n0 + wm * 32 + mt * 16 + g;
        #pragma unroll
        for (int nt = 0; nt < 8; nt++) {
            int col = wn * 64 + nt * 8 + tc * 2;
            if (col < NT) {
                float sc0 = sSc[col], sh0 = sSh[col];
                float sc1 = sSc[col + 1], sh1 = sSh[col + 1];
                float* a = acc[mt][nt];
                float y0 = a[0] * sc0 + sh0;
                float y1 = a[1] * sc1 + sh1;
                float y2 = a[2] * sc0 + sh0;
                float y3 = a[3] * sc1 + sh1;
                if (mode) {
                    y0 = fmaxf(y0, 0.f); y1 = fmaxf(y1, 0.f);
                    y2 = fmaxf(y2, 0.f); y3 = fmaxf(y3, 0.f);
                }
                *(float2*)(Y + (size_t)r0 * pitchY + nb0 + col)       = make_float2(y0, y1);
                *(float2*)(Y + (size_t)(r0 + 8) * pitchY + nb0 + col) = make_float2(y2, y3);
            }
        }
    }
}

// ============================ heads ============================
__global__ __launch_bounds__(256) void score_kernel(const float* __restrict__ s,
                                                    const float* __restrict__ w,
                                                    const float* __restrict__ b,
                                                    float* __restrict__ out)
{
    int wid = threadIdx.x >> 5, lid = threadIdx.x & 31;
    int p = blockIdx.x * 8 + wid;
    float4 v = *(const float4*)(s + (size_t)p * 128 + lid * 4);
    float4 ww = *(const float4*)(w + lid * 4);
    float sum = v.x * ww.x + v.y * ww.y + v.z * ww.z + v.w * ww.w;
    #pragma unroll
    for (int o = 16; o > 0; o >>= 1) sum += __shfl_xor_sync(0xffffffff, sum, o);
    if (lid == 0) out[p] = 1.f / (1.f + expf(-(sum + b[0])));
}

__global__ __launch_bounds__(256) void normalize_kernel(const float* __restrict__ fp,
                                                        float* __restrict__ out)
{
    int wid = threadIdx.x >> 5, lid = threadIdx.x & 31;
    int p = blockIdx.x * 8 + wid;
    float4 v = *(const float4*)(fp + (size_t)p * 128 + lid * 4);
    float ss = v.x * v.x + v.y * v.y + v.z * v.z + v.w * v.w;
    #pragma unroll
    for (int o = 16; o > 0; o >>= 1) ss += __shfl_xor_sync(0xffffffff, ss, o);
    float inv = 1.f / fmaxf(sqrtf(ss), 1e-12f);
    float4 r = make_float4(v.x * inv, v.y * inv, v.z * inv, v.w * inv);
    *(float4*)(out + (size_t)p * 128 + lid * 4) = r;
}

// ============================ launch ============================
extern "C" void kernel_launch(void* const* d_in, const int* in_sizes, int n_in,
                              void* d_out, int out_size)
{
    const float* pcd_xyz  = (const float*)d_in[0];
    const float* rgb_xyz  = (const float*)d_in[1];
    const float* pcd_feat = (const float*)d_in[2];
    const float* rgb_feat = (const float*)d_in[3];
    const float* cc1_w = (const float*)d_in[4];
    const float* cc1_b = (const float*)d_in[5];
    const float* cc_bn = (const float*)d_in[6];
    const float* cc2_w = (const float*)d_in[7];
    const float* cc2_b = (const float*)d_in[8];
    const float* co1_w = (const float*)d_in[9];
    const float* co1_b = (const float*)d_in[10];
    const float* co_bn = (const float*)d_in[11];
    const float* co2_w = (const float*)d_in[12];
    const float* co2_b = (const float*)d_in[13];
    const float* dh1_w = (const float*)d_in[14];
    const float* dh1_b = (const float*)d_in[15];
    const float* dh1_bn = (const float*)d_in[16];
    const float* dh2_w = (const float*)d_in[17];
    const float* dh2_b = (const float*)d_in[18];
    const float* dh2_bn = (const float*)d_in[19];
    const float* dh3_w = (const float*)d_in[20];
    const float* dh3_b = (const float*)d_in[21];
    const float* sh1_w = (const float*)d_in[22];
    const float* sh1_b = (const float*)d_in[23];
    const float* sh_bn = (const float*)d_in[24];
    const float* sh2_w = (const float*)d_in[25];
    const float* sh2_b = (const float*)d_in[26];

    float *xcat, *h1, *buf2, *co1o, *fullb, *d1, *d2, *fpb, *s1, *rgbT;
    int* idx;
    __half *whi, *wlo;
    cudaGetSymbolAddress((void**)&xcat,  g_xcat);
    cudaGetSymbolAddress((void**)&h1,    g_h1);
    cudaGetSymbolAddress((void**)&buf2,  g_buf2);
    cudaGetSymbolAddress((void**)&co1o,  g_co1);
    cudaGetSymbolAddress((void**)&fullb, g_full);
    cudaGetSymbolAddress((void**)&d1,    g_d1);
    cudaGetSymbolAddress((void**)&d2,    g_d2);
    cudaGetSymbolAddress((void**)&fpb,   g_fp);
    cudaGetSymbolAddress((void**)&s1,    g_s1);
    cudaGetSymbolAddress((void**)&rgbT,  g_rgbT);
    cudaGetSymbolAddress((void**)&idx,   g_idx);
    cudaGetSymbolAddress((void**)&whi,   g_whi);
    cudaGetSymbolAddress((void**)&wlo,   g_wlo);

    float* out = (float*)d_out;

    // weight plane offsets (elements)
    const int O_CC1 = 0,      O_CC2 = 147456, O_CO1 = 196608, O_CO2 = 262144;
    const int O_DH1 = 294912, O_DH2 = 325632, O_DH3 = 356352, O_SH1 = 380928;

    prep_all<<<(WTOT + 255) / 256, 256>>>(cc1_w, cc2_w, co1_w, co2_w,
                                          dh1_w, dh2_w, dh3_w, sh1_w, whi, wlo);

    knn_kernel<<<NP / 128, 256>>>(pcd_xyz, rgb_xyz, idx);
    transpose_rgb<<<dim3(NR / 32, 4), dim3(32, 8)>>>(rgb_feat, rgbT);
    tpose_pcd<<<NP / 32, dim3(32, 8)>>>(pcd_feat, fullb);
    gather_kernel<<<NP * 3 * 32 / 256, 256>>>(rgbT, idx, xcat);
    maxfeat_kernel<<<NP * 32 / 256, 256>>>(rgbT, idx, buf2);

    gemm_hmma<<<dim3(128, 3), 256>>>(xcat, 384, 384, 384, whi + O_CC1, wlo + O_CC1, 384, h1,         384, cc1_b, cc_bn,  1);
    gemm_hmma<<<dim3(128, 1), 256>>>(h1,   384, 384, 384, whi + O_CC2, wlo + O_CC2, 128, buf2,       256, cc2_b, nullptr, 0);
    gemm_hmma<<<dim3(128, 2), 256>>>(buf2, 256, 256, 256, whi + O_CO1, wlo + O_CO1, 256, co1o,       256, co1_b, co_bn,  1);
    gemm_hmma<<<dim3(128, 1), 256>>>(co1o, 256, 256, 256, whi + O_CO2, wlo + O_CO2, 128, fullb + 32, 160, co2_b, nullptr, 0);
    gemm_hmma<<<dim3(128, 2), 256>>>(fullb,160, 160, 192, whi + O_DH1, wlo + O_DH1, 160, d1,         160, dh1_b, dh1_bn, 1);
    gemm_hmma<<<dim3(128, 2), 256>>>(d1,   160, 160, 192, whi + O_DH2, wlo + O_DH2, 160, d2,         160, dh2_b, dh2_bn, 1);
    gemm_hmma<<<dim3(128, 1), 256>>>(d2,   160, 160, 192, whi + O_DH3, wlo + O_DH3, 128, fpb,        128, dh3_b, nullptr, 0);
    gemm_hmma<<<dim3(128, 1), 256>>>(fpb,  128, 128, 128, whi + O_SH1, wlo + O_SH1, 128, s1,         128, sh1_b, sh_bn,  1);

    // outputs: [pcd_xyz (NP*3)] [vote_scores (NP)] [vf (NP,128)]
    score_kernel<<<NP / 8, 256>>>(s1, sh2_w, sh2_b, out + NP * 3);
    normalize_kernel<<<NP / 8, 256>>>(fpb, out + NP * 3 + NP);
    cudaMemcpyAsync(out, pcd_xyz, NP * 3 * sizeof(float), cudaMemcpyDeviceToDevice, 0);
}